// round 3
// baseline (speedup 1.0000x reference)
#include <cuda_runtime.h>
#include <math.h>

#define NN 100000
#define EE 1600000

struct __align__(32) Rec {
    float4 ppf;            // dist, a1, a2, a3
    int    col;
    int    pad0, pad1, pad2;
};

// Scratch (device globals; no allocation allowed)
__device__ float  g_xw[(size_t)NN * 64];    // x@W1[:64] + b1
__device__ Rec    g_rec[EE];                // CSR-ordered edge records (32B each)
__device__ int    g_deg[NN];
__device__ int    g_off[NN + 1];
__device__ int    g_cur[NN];
__device__ int    g_bsum[128];              // per-1024-chunk block sums
__device__ double g_sum;
__device__ float  g_invmean;

// ---------------------------------------------------------------- zero
__global__ void k_zero(int n) {
    int i = blockIdx.x * 256 + threadIdx.x;
    if (i < n) g_deg[i] = 0;
    if (i == 0) g_sum = 0.0;
}

// ---------------------------------------------------------------- per-edge: degree counts + sq-dist sum
__global__ void k_prep(const int* __restrict__ ei, const float* __restrict__ pos, int E) {
    int e = blockIdx.x * 256 + threadIdx.x;
    float dist = 0.f;
    if (e < E) {
        int r = ei[e], c = ei[E + e];
        float dx = pos[c * 3 + 0] - pos[r * 3 + 0];
        float dy = pos[c * 3 + 1] - pos[r * 3 + 1];
        float dz = pos[c * 3 + 2] - pos[r * 3 + 2];
        dist = dx * dx + dy * dy + dz * dz;
        atomicAdd(&g_deg[r], 1);
    }
#pragma unroll
    for (int o = 16; o > 0; o >>= 1) dist += __shfl_down_sync(0xffffffffu, dist, o);
    __shared__ float wpart[8];
    int lane = threadIdx.x & 31, wid = threadIdx.x >> 5;
    if (lane == 0) wpart[wid] = dist;
    __syncthreads();
    if (threadIdx.x == 0) {
        float s = 0.f;
#pragma unroll
        for (int i = 0; i < 8; i++) s += wpart[i];
        atomicAdd(&g_sum, (double)s);
    }
}

// ---------------------------------------------------------------- multi-block exclusive scan
__global__ void k_scan1(int n) {
    int base = blockIdx.x * 1024 + threadIdx.x * 4;
    int d0 = 0, d1 = 0, d2 = 0, d3 = 0;
    if (base + 3 < n) {
        int4 v = *(const int4*)&g_deg[base];
        d0 = v.x; d1 = v.y; d2 = v.z; d3 = v.w;
    } else {
        if (base + 0 < n) d0 = g_deg[base + 0];
        if (base + 1 < n) d1 = g_deg[base + 1];
        if (base + 2 < n) d2 = g_deg[base + 2];
        if (base + 3 < n) d3 = g_deg[base + 3];
    }
    int s = d0 + d1 + d2 + d3;
    int lane = threadIdx.x & 31, wid = threadIdx.x >> 5;
    int v = s;
#pragma unroll
    for (int o = 1; o < 32; o <<= 1) {
        int y = __shfl_up_sync(0xffffffffu, v, o);
        if (lane >= o) v += y;
    }
    __shared__ int ws[8];
    if (lane == 31) ws[wid] = v;
    __syncthreads();
    if (threadIdx.x == 0) {
        int run = 0;
#pragma unroll
        for (int i = 0; i < 8; i++) { int t = ws[i]; ws[i] = run; run += t; }
        g_bsum[blockIdx.x] = run;
    }
    __syncthreads();
    int excl = v - s + ws[wid];
    if (base + 0 < n) g_off[base + 0] = excl;
    if (base + 1 < n) g_off[base + 1] = excl + d0;
    if (base + 2 < n) g_off[base + 2] = excl + d0 + d1;
    if (base + 3 < n) g_off[base + 3] = excl + d0 + d1 + d2;
}

// ---------------------------------------------------------------- xw = x @ W1[:64,:] + b1
// (launched 4th so the profiler captures it)
__global__ void k_xw(const float* __restrict__ x, const float* __restrict__ W1,
                     const float* __restrict__ b1, int n) {
    __shared__ float xs[64][65];
    __shared__ float ws[64][64];
    int n0 = blockIdx.x * 64;
    for (int i = threadIdx.x; i < 4096; i += 256) ws[i >> 6][i & 63] = W1[i];
    for (int i = threadIdx.x; i < 4096; i += 256) {
        int r = i >> 6, c = i & 63;
        xs[r][c] = (n0 + r < n) ? x[(size_t)(n0 + r) * 64 + c] : 0.f;
    }
    __syncthreads();
    int tx = threadIdx.x & 15, ty = threadIdx.x >> 4;
    float acc[4][4];
#pragma unroll
    for (int j = 0; j < 4; j++) {
        float b = b1[tx * 4 + j];
#pragma unroll
        for (int i = 0; i < 4; i++) acc[i][j] = b;
    }
#pragma unroll 16
    for (int d = 0; d < 64; d++) {
        float a[4];
#pragma unroll
        for (int i = 0; i < 4; i++) a[i] = xs[ty * 4 + i][d];
        float4 w = *(const float4*)&ws[d][tx * 4];
#pragma unroll
        for (int i = 0; i < 4; i++) {
            acc[i][0] = fmaf(a[i], w.x, acc[i][0]);
            acc[i][1] = fmaf(a[i], w.y, acc[i][1]);
            acc[i][2] = fmaf(a[i], w.z, acc[i][2]);
            acc[i][3] = fmaf(a[i], w.w, acc[i][3]);
        }
    }
#pragma unroll
    for (int i = 0; i < 4; i++) {
        int node = n0 + ty * 4 + i;
        if (node < n) {
            float4 v = make_float4(acc[i][0], acc[i][1], acc[i][2], acc[i][3]);
            *(float4*)&g_xw[(size_t)node * 64 + tx * 4] = v;
        }
    }
}

// Stage 2: scan the (<=128) block sums; finalize normalizer.
__global__ void k_scan2(int nb, int n, int E) {
    int t = threadIdx.x;  // blockDim = 128
    int s = (t < nb) ? g_bsum[t] : 0;
    int lane = t & 31, wid = t >> 5;
    int v = s;
#pragma unroll
    for (int o = 1; o < 32; o <<= 1) {
        int y = __shfl_up_sync(0xffffffffu, v, o);
        if (lane >= o) v += y;
    }
    __shared__ int ws[4];
    if (lane == 31) ws[wid] = v;
    __syncthreads();
    if (t == 0) {
        int run = 0;
#pragma unroll
        for (int i = 0; i < 4; i++) { int x = ws[i]; ws[i] = run; run += x; }
    }
    __syncthreads();
    int excl = v - s + ws[wid];
    if (t < nb) g_bsum[t] = excl;
    if (t == 0) {
        g_off[n] = E;
        g_invmean = (float)((double)(E + n) / g_sum);
    }
}

// Stage 3: add block offsets; init g_cur.
__global__ void k_scan3(int n) {
    int i = blockIdx.x * 256 + threadIdx.x;
    if (i >= n) return;
    int o = g_off[i] + g_bsum[i >> 10];
    g_off[i] = o;
    g_cur[i] = o;
}

// ---------------------------------------------------------------- ppf + scatter into CSR (packed 32B records)
__device__ __forceinline__ float ppf_angle(float ax, float ay, float az,
                                           float bx, float by, float bz) {
    float cx = ay * bz - az * by;
    float cy = az * bx - ax * bz;
    float cz = ax * by - ay * bx;
    float dot = ax * bx + ay * by + az * bz;
    return atan2f(sqrtf(cx * cx + cy * cy + cz * cz), dot);
}

__global__ void k_scatter(const int* __restrict__ ei, const float* __restrict__ pos,
                          const float* __restrict__ nrm, int E) {
    int e = blockIdx.x * 256 + threadIdx.x;
    if (e >= E) return;
    int r = ei[e], c = ei[E + e];
    float dx = pos[c * 3 + 0] - pos[r * 3 + 0];
    float dy = pos[c * 3 + 1] - pos[r * 3 + 1];
    float dz = pos[c * 3 + 2] - pos[r * 3 + 2];
    float n1x = nrm[r * 3 + 0], n1y = nrm[r * 3 + 1], n1z = nrm[r * 3 + 2];
    float n2x = nrm[c * 3 + 0], n2y = nrm[c * 3 + 1], n2z = nrm[c * 3 + 2];
    float dist = (dx * dx + dy * dy + dz * dz) * g_invmean;
    float a1 = ppf_angle(n1x, n1y, n1z, dx, dy, dz);
    float a2 = ppf_angle(n2x, n2y, n2z, dx, dy, dz);
    float a3 = ppf_angle(n1x, n1y, n1z, n2x, n2y, n2z);
    int p = atomicAdd(&g_cur[r], 1);
    // one 32B-aligned record -> single DRAM sector per edge
    float4* dst = (float4*)&g_rec[p];
    dst[0] = make_float4(dist, a1, a2, a3);
    dst[1] = make_float4(__int_as_float(c), 0.f, 0.f, 0.f);
}

// ---------------------------------------------------------------- fused: segment-max + out = relu(seg @ W2 + b2)
// Persistent blocks: W2 (32KB) + b2 loaded into smem ONCE per block.
// Warp per node: lane owns dims [2*lane, 2*lane+1] of the 64-dim max,
// then the warp does the 64x128 GEMV via shfl broadcast.
__global__ void __launch_bounds__(256) k_node_out(const float* __restrict__ W1,
                                                  const float* __restrict__ W2,
                                                  const float* __restrict__ b2,
                                                  float* __restrict__ out, int n) {
    __shared__ float ws[64 * 128];
    __shared__ float bs[128];
    for (int i = threadIdx.x; i < 64 * 128; i += 256) ws[i] = W2[i];
    if (threadIdx.x < 128) bs[threadIdx.x] = b2[threadIdx.x];
    __syncthreads();

    int lane = threadIdx.x & 31;
    int wid  = threadIdx.x >> 5;

    const float* Wp = W1 + 64 * 64;
    float2 w0 = *(const float2*)&Wp[0 * 64 + lane * 2];
    float2 w1 = *(const float2*)&Wp[1 * 64 + lane * 2];
    float2 w2 = *(const float2*)&Wp[2 * 64 + lane * 2];
    float2 w3 = *(const float2*)&Wp[3 * 64 + lane * 2];

    float4 bb = *(const float4*)&bs[lane * 4];

    for (int node = blockIdx.x * 8 + wid; node < n; node += gridDim.x * 8) {
        float2 xw = *(const float2*)&g_xw[(size_t)node * 64 + lane * 2];
        float ax = fmaxf(xw.x, 0.f);   // self-loop: ppf == 0 exactly
        float ay = fmaxf(xw.y, 0.f);

        int beg = g_off[node];
        int end = g_off[node + 1];
        int i = beg;
        for (; i + 1 < end; i += 2) {
            const float4* r0 = (const float4*)&g_rec[i];
            const float4* r1 = (const float4*)&g_rec[i + 1];
            float4 p0 = r0[0];
            float4 p1 = r1[0];
            int c0 = __float_as_int(r0[1].x);
            int c1 = __float_as_int(r1[1].x);
            float2 xc0 = *(const float2*)&g_xw[(size_t)c0 * 64 + lane * 2];
            float2 xc1 = *(const float2*)&g_xw[(size_t)c1 * 64 + lane * 2];
            float hx0 = fmaf(p0.x, w0.x, fmaf(p0.y, w1.x, fmaf(p0.z, w2.x, fmaf(p0.w, w3.x, xc0.x))));
            float hy0 = fmaf(p0.x, w0.y, fmaf(p0.y, w1.y, fmaf(p0.z, w2.y, fmaf(p0.w, w3.y, xc0.y))));
            float hx1 = fmaf(p1.x, w0.x, fmaf(p1.y, w1.x, fmaf(p1.z, w2.x, fmaf(p1.w, w3.x, xc1.x))));
            float hy1 = fmaf(p1.x, w0.y, fmaf(p1.y, w1.y, fmaf(p1.z, w2.y, fmaf(p1.w, w3.y, xc1.y))));
            ax = fmaxf(ax, fmaxf(hx0, hx1));
            ay = fmaxf(ay, fmaxf(hy0, hy1));
        }
        if (i < end) {
            const float4* r0 = (const float4*)&g_rec[i];
            float4 p = r0[0];
            int c = __float_as_int(r0[1].x);
            float2 xc = *(const float2*)&g_xw[(size_t)c * 64 + lane * 2];
            float hx = fmaf(p.x, w0.x, fmaf(p.y, w1.x, fmaf(p.z, w2.x, fmaf(p.w, w3.x, xc.x))));
            float hy = fmaf(p.x, w0.y, fmaf(p.y, w1.y, fmaf(p.z, w2.y, fmaf(p.w, w3.y, xc.y))));
            ax = fmaxf(ax, hx);
            ay = fmaxf(ay, hy);
        }

        // GEMV: out[node, lane*4 .. lane*4+3] = relu(sum_d seg_d * W2[d,:] + b2)
        float4 acc = bb;
#pragma unroll
        for (int j = 0; j < 32; j++) {
            float s0 = __shfl_sync(0xffffffffu, ax, j);   // dim 2j
            float s1 = __shfl_sync(0xffffffffu, ay, j);   // dim 2j+1
            float4 wA = *(const float4*)&ws[(2 * j) * 128 + lane * 4];
            float4 wB = *(const float4*)&ws[(2 * j + 1) * 128 + lane * 4];
            acc.x = fmaf(s0, wA.x, fmaf(s1, wB.x, acc.x));
            acc.y = fmaf(s0, wA.y, fmaf(s1, wB.y, acc.y));
            acc.z = fmaf(s0, wA.z, fmaf(s1, wB.z, acc.z));
            acc.w = fmaf(s0, wA.w, fmaf(s1, wB.w, acc.w));
        }
        float4 o = make_float4(fmaxf(acc.x, 0.f), fmaxf(acc.y, 0.f),
                               fmaxf(acc.z, 0.f), fmaxf(acc.w, 0.f));
        *(float4*)&out[(size_t)node * 128 + lane * 4] = o;
    }
}

// ---------------------------------------------------------------- launch
extern "C" void kernel_launch(void* const* d_in, const int* in_sizes, int n_in,
                              void* d_out, int out_size) {
    const float* x   = (const float*)d_in[0];
    const float* pos = (const float*)d_in[1];
    const float* nrm = (const float*)d_in[2];
    const int*   ei  = (const int*)d_in[3];
    // d_in[4] = batch (unused)
    const float* W1  = (const float*)d_in[5];
    const float* b1  = (const float*)d_in[6];
    const float* W2  = (const float*)d_in[7];
    const float* b2  = (const float*)d_in[8];
    float* out = (float*)d_out;

    int N = in_sizes[1] / 3;
    int E = in_sizes[3] / 2;
    int nb = (N + 1023) / 1024;

    k_zero<<<(N + 255) / 256, 256>>>(N);
    k_prep<<<(E + 255) / 256, 256>>>(ei, pos, E);
    k_scan1<<<nb, 256>>>(N);
    k_xw<<<(N + 63) / 64, 256>>>(x, W1, b1, N);   // launch #4 -> profiled
    k_scan2<<<1, 128>>>(nb, N, E);
    k_scan3<<<(N + 255) / 256, 256>>>(N);
    k_scatter<<<(E + 255) / 256, 256>>>(ei, pos, nrm, E);
    k_node_out<<<592, 256>>>(W1, W2, b2, out, N);
}

// round 5
// speedup vs baseline: 1.3077x; 1.3077x over previous
#include <cuda_runtime.h>
#include <math.h>

#define NN 100000
#define EE 1600000

struct __align__(32) Rec {
    float4 ppf;            // raw sq-dist, a1, a2, a3
    int    col;
    int    pad0, pad1, pad2;
};

// Scratch (device globals; no allocation allowed)
__device__ float  g_xw[(size_t)NN * 64];    // x@W1[:64] + b1
__device__ Rec    g_rec[EE];                // CSR-ordered edge records (32B each)
__device__ int    g_deg[NN];
__device__ int    g_off[NN + 1];
__device__ int    g_cur[NN];
__device__ int    g_bsum[128];
__device__ double g_sum;
__device__ float  g_invmean;

__device__ __forceinline__ unsigned long long ffma2(unsigned long long a,
                                                    unsigned long long b,
                                                    unsigned long long c) {
    unsigned long long d;
    asm("fma.rn.f32x2 %0, %1, %2, %3;" : "=l"(d) : "l"(a), "l"(b), "l"(c));
    return d;
}
__device__ __forceinline__ unsigned long long pack2(float lo, float hi) {
    unsigned long long r;
    asm("mov.b64 %0, {%1, %2};" : "=l"(r) : "f"(lo), "f"(hi));
    return r;
}
__device__ __forceinline__ float2 unpack2(unsigned long long v) {
    float lo, hi;
    asm("mov.b64 {%0, %1}, %2;" : "=f"(lo), "=f"(hi) : "l"(v));
    return make_float2(lo, hi);
}

// ---------------------------------------------------------------- zero
__global__ void k_zero(int n) {
    int i = blockIdx.x * 256 + threadIdx.x;
    if (i < n) g_deg[i] = 0;
    if (i == 0) g_sum = 0.0;
}

// ---------------------------------------------------------------- degree count only
__global__ void k_prep(const int* __restrict__ ei, int E) {
    int e = blockIdx.x * 256 + threadIdx.x;
    if (e < E) atomicAdd(&g_deg[ei[e]], 1);
}

// ---------------------------------------------------------------- multi-block exclusive scan
__global__ void k_scan1(int n) {
    int base = blockIdx.x * 1024 + threadIdx.x * 4;
    int d0 = 0, d1 = 0, d2 = 0, d3 = 0;
    if (base + 3 < n) {
        int4 v = *(const int4*)&g_deg[base];
        d0 = v.x; d1 = v.y; d2 = v.z; d3 = v.w;
    } else {
        if (base + 0 < n) d0 = g_deg[base + 0];
        if (base + 1 < n) d1 = g_deg[base + 1];
        if (base + 2 < n) d2 = g_deg[base + 2];
        if (base + 3 < n) d3 = g_deg[base + 3];
    }
    int s = d0 + d1 + d2 + d3;
    int lane = threadIdx.x & 31, wid = threadIdx.x >> 5;
    int v = s;
#pragma unroll
    for (int o = 1; o < 32; o <<= 1) {
        int y = __shfl_up_sync(0xffffffffu, v, o);
        if (lane >= o) v += y;
    }
    __shared__ int ws[8];
    if (lane == 31) ws[wid] = v;
    __syncthreads();
    if (threadIdx.x == 0) {
        int run = 0;
#pragma unroll
        for (int i = 0; i < 8; i++) { int t = ws[i]; ws[i] = run; run += t; }
        g_bsum[blockIdx.x] = run;
    }
    __syncthreads();
    int excl = v - s + ws[wid];
    if (base + 0 < n) g_off[base + 0] = excl;
    if (base + 1 < n) g_off[base + 1] = excl + d0;
    if (base + 2 < n) g_off[base + 2] = excl + d0 + d1;
    if (base + 3 < n) g_off[base + 3] = excl + d0 + d1 + d2;
}

// ---------------------------------------------------------------- xw = x @ W1[:64,:] + b1
// xs stored TRANSPOSED [dim][node] (stride 68) so a-fetch is one LDS.128.
__global__ void k_xw(const float* __restrict__ x, const float* __restrict__ W1,
                     const float* __restrict__ b1, int n) {
    __shared__ float xs[64 * 68];
    __shared__ float ws[64 * 64];
    int n0 = blockIdx.x * 64;
    for (int i = threadIdx.x; i < 4096; i += 256) ws[i] = W1[i];
    for (int i = threadIdx.x; i < 4096; i += 256) {
        int r = i >> 6, c = i & 63;
        xs[c * 68 + r] = (n0 + r < n) ? x[(size_t)(n0 + r) * 64 + c] : 0.f;
    }
    __syncthreads();
    int tx = threadIdx.x & 15, ty = threadIdx.x >> 4;
    float acc[4][4];
#pragma unroll
    for (int j = 0; j < 4; j++) {
        float b = b1[tx * 4 + j];
#pragma unroll
        for (int i = 0; i < 4; i++) acc[i][j] = b;
    }
#pragma unroll 16
    for (int d = 0; d < 64; d++) {
        float4 a = *(const float4*)&xs[d * 68 + ty * 4];
        float4 w = *(const float4*)&ws[d * 64 + tx * 4];
        acc[0][0] = fmaf(a.x, w.x, acc[0][0]); acc[0][1] = fmaf(a.x, w.y, acc[0][1]);
        acc[0][2] = fmaf(a.x, w.z, acc[0][2]); acc[0][3] = fmaf(a.x, w.w, acc[0][3]);
        acc[1][0] = fmaf(a.y, w.x, acc[1][0]); acc[1][1] = fmaf(a.y, w.y, acc[1][1]);
        acc[1][2] = fmaf(a.y, w.z, acc[1][2]); acc[1][3] = fmaf(a.y, w.w, acc[1][3]);
        acc[2][0] = fmaf(a.z, w.x, acc[2][0]); acc[2][1] = fmaf(a.z, w.y, acc[2][1]);
        acc[2][2] = fmaf(a.z, w.z, acc[2][2]); acc[2][3] = fmaf(a.z, w.w, acc[2][3]);
        acc[3][0] = fmaf(a.w, w.x, acc[3][0]); acc[3][1] = fmaf(a.w, w.y, acc[3][1]);
        acc[3][2] = fmaf(a.w, w.z, acc[3][2]); acc[3][3] = fmaf(a.w, w.w, acc[3][3]);
    }
#pragma unroll
    for (int i = 0; i < 4; i++) {
        int node = n0 + ty * 4 + i;
        if (node < n) {
            float4 v = make_float4(acc[i][0], acc[i][1], acc[i][2], acc[i][3]);
            *(float4*)&g_xw[(size_t)node * 64 + tx * 4] = v;
        }
    }
}

// Stage 2: scan block sums; g_off[n]=E.
__global__ void k_scan2(int nb, int n, int E) {
    int t = threadIdx.x;  // blockDim = 128
    int s = (t < nb) ? g_bsum[t] : 0;
    int lane = t & 31, wid = t >> 5;
    int v = s;
#pragma unroll
    for (int o = 1; o < 32; o <<= 1) {
        int y = __shfl_up_sync(0xffffffffu, v, o);
        if (lane >= o) v += y;
    }
    __shared__ int ws[4];
    if (lane == 31) ws[wid] = v;
    __syncthreads();
    if (t == 0) {
        int run = 0;
#pragma unroll
        for (int i = 0; i < 4; i++) { int x = ws[i]; ws[i] = run; run += x; }
    }
    __syncthreads();
    int excl = v - s + ws[wid];
    if (t < nb) g_bsum[t] = excl;
    if (t == 0) g_off[n] = E;
}

// Stage 3: add block offsets; init g_cur.
__global__ void k_scan3(int n) {
    int i = blockIdx.x * 256 + threadIdx.x;
    if (i >= n) return;
    int o = g_off[i] + g_bsum[i >> 10];
    g_off[i] = o;
    g_cur[i] = o;
}

// ---------------------------------------------------------------- ppf + scatter + dist sum
__device__ __forceinline__ float ppf_angle(float ax, float ay, float az,
                                           float bx, float by, float bz) {
    float cx = ay * bz - az * by;
    float cy = az * bx - ax * bz;
    float cz = ax * by - ay * bx;
    float dot = ax * bx + ay * by + az * bz;
    return atan2f(sqrtf(cx * cx + cy * cy + cz * cz), dot);
}

__global__ void k_scatter(const int* __restrict__ ei, const float* __restrict__ pos,
                          const float* __restrict__ nrm, int E) {
    int e = blockIdx.x * 256 + threadIdx.x;
    float dist = 0.f;
    if (e < E) {
        int r = ei[e], c = ei[E + e];
        float dx = pos[c * 3 + 0] - pos[r * 3 + 0];
        float dy = pos[c * 3 + 1] - pos[r * 3 + 1];
        float dz = pos[c * 3 + 2] - pos[r * 3 + 2];
        float n1x = nrm[r * 3 + 0], n1y = nrm[r * 3 + 1], n1z = nrm[r * 3 + 2];
        float n2x = nrm[c * 3 + 0], n2y = nrm[c * 3 + 1], n2z = nrm[c * 3 + 2];
        dist = dx * dx + dy * dy + dz * dz;
        float a1 = ppf_angle(n1x, n1y, n1z, dx, dy, dz);
        float a2 = ppf_angle(n2x, n2y, n2z, dx, dy, dz);
        float a3 = ppf_angle(n1x, n1y, n1z, n2x, n2y, n2z);
        int p = atomicAdd(&g_cur[r], 1);
        float4* dst = (float4*)&g_rec[p];
        dst[0] = make_float4(dist, a1, a2, a3);   // raw dist; normalized in k_node_out
        dst[1] = make_float4(__int_as_float(c), 0.f, 0.f, 0.f);
    }
#pragma unroll
    for (int o = 16; o > 0; o >>= 1) dist += __shfl_down_sync(0xffffffffu, dist, o);
    __shared__ float wpart[8];
    int lane = threadIdx.x & 31, wid = threadIdx.x >> 5;
    if (lane == 0) wpart[wid] = dist;
    __syncthreads();
    if (threadIdx.x == 0) {
        float s = 0.f;
#pragma unroll
        for (int i = 0; i < 8; i++) s += wpart[i];
        atomicAdd(&g_sum, (double)s);
    }
}

// ---------------------------------------------------------------- normalizer
__global__ void k_mean(int n, int E) {
    g_invmean = (float)((double)(E + n) / g_sum);
}

// ---------------------------------------------------------------- fused: segmax (4 nodes/warp) + relu(seg @ W2 + b2)
// W2 in smem once per block; segmax staged as DUPLICATED pairs so the GEMV
// amortizes each W2 LDS.128 over 4 nodes and uses fma.rn.f32x2.
__global__ void __launch_bounds__(256) k_node_out(const float* __restrict__ W1,
                                                  const float* __restrict__ W2,
                                                  const float* __restrict__ b2,
                                                  float* __restrict__ out, int n) {
    __shared__ float ws[64 * 128];
    __shared__ float sdup[8][4 * 128];   // [warp][node k][dup dims]
    for (int i = threadIdx.x; i < 64 * 128; i += 256) ws[i] = W2[i];
    __syncthreads();

    int lane = threadIdx.x & 31;
    int wid  = threadIdx.x >> 5;

    const float* Wp = W1 + 64 * 64;
    float2 w0 = *(const float2*)&Wp[0 * 64 + lane * 2];
    float2 w1 = *(const float2*)&Wp[1 * 64 + lane * 2];
    float2 w2 = *(const float2*)&Wp[2 * 64 + lane * 2];
    float2 w3 = *(const float2*)&Wp[3 * 64 + lane * 2];
    float4 bq = *(const float4*)&b2[lane * 4];
    unsigned long long bb0 = pack2(bq.x, bq.y);
    unsigned long long bb1 = pack2(bq.z, bq.w);
    float inv = g_invmean;

    int step = gridDim.x * 8 * 4;
    for (int base = (blockIdx.x * 8 + wid) * 4; base < n; base += step) {
        // phase 1: segment-max for 4 consecutive nodes
#pragma unroll
        for (int k = 0; k < 4; k++) {
            int node = base + k;
            float ax = 0.f, ay = 0.f;
            if (node < n) {
                float2 xw = *(const float2*)&g_xw[(size_t)node * 64 + lane * 2];
                ax = fmaxf(xw.x, 0.f);   // self-loop: ppf == 0 exactly
                ay = fmaxf(xw.y, 0.f);
                int beg = g_off[node];
                int end = g_off[node + 1];
                int i = beg;
                for (; i + 1 < end; i += 2) {
                    const float4* r0 = (const float4*)&g_rec[i];
                    const float4* r1 = (const float4*)&g_rec[i + 1];
                    float4 p0 = r0[0];
                    float4 p1 = r1[0];
                    int c0 = __float_as_int(r0[1].x);
                    int c1 = __float_as_int(r1[1].x);
                    float2 xc0 = *(const float2*)&g_xw[(size_t)c0 * 64 + lane * 2];
                    float2 xc1 = *(const float2*)&g_xw[(size_t)c1 * 64 + lane * 2];
                    float px0 = p0.x * inv, px1 = p1.x * inv;
                    float hx0 = fmaf(px0, w0.x, fmaf(p0.y, w1.x, fmaf(p0.z, w2.x, fmaf(p0.w, w3.x, xc0.x))));
                    float hy0 = fmaf(px0, w0.y, fmaf(p0.y, w1.y, fmaf(p0.z, w2.y, fmaf(p0.w, w3.y, xc0.y))));
                    float hx1 = fmaf(px1, w0.x, fmaf(p1.y, w1.x, fmaf(p1.z, w2.x, fmaf(p1.w, w3.x, xc1.x))));
                    float hy1 = fmaf(px1, w0.y, fmaf(p1.y, w1.y, fmaf(p1.z, w2.y, fmaf(p1.w, w3.y, xc1.y))));
                    ax = fmaxf(ax, fmaxf(hx0, hx1));
                    ay = fmaxf(ay, fmaxf(hy0, hy1));
                }
                if (i < end) {
                    const float4* r0 = (const float4*)&g_rec[i];
                    float4 p = r0[0];
                    int c = __float_as_int(r0[1].x);
                    float2 xc = *(const float2*)&g_xw[(size_t)c * 64 + lane * 2];
                    float px = p.x * inv;
                    float hx = fmaf(px, w0.x, fmaf(p.y, w1.x, fmaf(p.z, w2.x, fmaf(p.w, w3.x, xc.x))));
                    float hy = fmaf(px, w0.y, fmaf(p.y, w1.y, fmaf(p.z, w2.y, fmaf(p.w, w3.y, xc.y))));
                    ax = fmaxf(ax, hx);
                    ay = fmaxf(ay, hy);
                }
            }
            // duplicated-pair staging: dims 2l,2l+1 -> {ax,ax,ay,ay} at [4l]
            *(float4*)&sdup[wid][k * 128 + lane * 4] = make_float4(ax, ax, ay, ay);
        }
        __syncwarp();

        // phase 2: GEMV for 4 nodes with shared W2 reads + f32x2
        unsigned long long a0x = bb0, a0y = bb1;
        unsigned long long a1x = bb0, a1y = bb1;
        unsigned long long a2x = bb0, a2y = bb1;
        unsigned long long a3x = bb0, a3y = bb1;
#pragma unroll 8
        for (int jp = 0; jp < 32; jp++) {
            float4 wAf = *(const float4*)&ws[(2 * jp) * 128 + lane * 4];
            float4 wBf = *(const float4*)&ws[(2 * jp + 1) * 128 + lane * 4];
            float4 s0f = *(const float4*)&sdup[wid][0 * 128 + jp * 4];
            float4 s1f = *(const float4*)&sdup[wid][1 * 128 + jp * 4];
            float4 s2f = *(const float4*)&sdup[wid][2 * 128 + jp * 4];
            float4 s3f = *(const float4*)&sdup[wid][3 * 128 + jp * 4];
            unsigned long long wAx = pack2(wAf.x, wAf.y), wAy = pack2(wAf.z, wAf.w);
            unsigned long long wBx = pack2(wBf.x, wBf.y), wBy = pack2(wBf.z, wBf.w);
            unsigned long long s0a = pack2(s0f.x, s0f.y), s0b = pack2(s0f.z, s0f.w);
            unsigned long long s1a = pack2(s1f.x, s1f.y), s1b = pack2(s1f.z, s1f.w);
            unsigned long long s2a = pack2(s2f.x, s2f.y), s2b = pack2(s2f.z, s2f.w);
            unsigned long long s3a = pack2(s3f.x, s3f.y), s3b = pack2(s3f.z, s3f.w);
            a0x = ffma2(s0a, wAx, a0x); a0y = ffma2(s0a, wAy, a0y);
            a0x = ffma2(s0b, wBx, a0x); a0y = ffma2(s0b, wBy, a0y);
            a1x = ffma2(s1a, wAx, a1x); a1y = ffma2(s1a, wAy, a1y);
            a1x = ffma2(s1b, wBx, a1x); a1y = ffma2(s1b, wBy, a1y);
            a2x = ffma2(s2a, wAx, a2x); a2y = ffma2(s2a, wAy, a2y);
            a2x = ffma2(s2b, wBx, a2x); a2y = ffma2(s2b, wBy, a2y);
            a3x = ffma2(s3a, wAx, a3x); a3y = ffma2(s3a, wAy, a3y);
            a3x = ffma2(s3b, wBx, a3x); a3y = ffma2(s3b, wBy, a3y);
        }
        __syncwarp();

        unsigned long long rx[4] = {a0x, a1x, a2x, a3x};
        unsigned long long ry[4] = {a0y, a1y, a2y, a3y};
#pragma unroll
        for (int k = 0; k < 4; k++) {
            int node = base + k;
            if (node < n) {
                float2 lo = unpack2(rx[k]);
                float2 hi = unpack2(ry[k]);
                float4 o = make_float4(fmaxf(lo.x, 0.f), fmaxf(lo.y, 0.f),
                                       fmaxf(hi.x, 0.f), fmaxf(hi.y, 0.f));
                *(float4*)&out[(size_t)node * 128 + lane * 4] = o;
            }
        }
    }
}

// ---------------------------------------------------------------- launch
extern "C" void kernel_launch(void* const* d_in, const int* in_sizes, int n_in,
                              void* d_out, int out_size) {
    const float* x   = (const float*)d_in[0];
    const float* pos = (const float*)d_in[1];
    const float* nrm = (const float*)d_in[2];
    const int*   ei  = (const int*)d_in[3];
    // d_in[4] = batch (unused)
    const float* W1  = (const float*)d_in[5];
    const float* b1  = (const float*)d_in[6];
    const float* W2  = (const float*)d_in[7];
    const float* b2  = (const float*)d_in[8];
    float* out = (float*)d_out;

    int N = in_sizes[1] / 3;
    int E = in_sizes[3] / 2;
    int nb = (N + 1023) / 1024;

    k_zero<<<(N + 255) / 256, 256>>>(N);
    k_prep<<<(E + 255) / 256, 256>>>(ei, E);
    k_scan1<<<nb, 256>>>(N);
    k_xw<<<(N + 63) / 64, 256>>>(x, W1, b1, N);   // launch #4 -> profiled
    k_scan2<<<1, 128>>>(nb, N, E);
    k_scan3<<<(N + 255) / 256, 256>>>(N);
    k_scatter<<<(E + 255) / 256, 256>>>(ei, pos, nrm, E);
    k_mean<<<1, 1>>>(N, E);
    k_node_out<<<592, 256>>>(W1, W2, b2, out, N);
}

// round 7
// speedup vs baseline: 1.4912x; 1.1404x over previous
#include <cuda_runtime.h>
#include <math.h>

#define NN 100000
#define EE 1600000

struct __align__(32) Rec {
    float4 ppf;            // raw sq-dist, a1, a2, a3
    int    col;
    int    pad0, pad1, pad2;
};

// Scratch (device globals; no allocation allowed)
__device__ float  g_xw[(size_t)NN * 64];    // x@W1[:64] + b1
__device__ Rec    g_rec[EE];                // CSR-ordered edge records (32B each)
__device__ float4 g_pn[(size_t)NN * 2];     // packed {pos,0},{nrm,0} per node
__device__ int    g_deg[NN];
__device__ int    g_off[NN + 1];
__device__ int    g_cur[NN];
__device__ int    g_bsum[128];
__device__ double g_sum;
__device__ float  g_invmean;

typedef unsigned long long u64;

__device__ __forceinline__ u64 ffma2(u64 a, u64 b, u64 c) {
    u64 d;
    asm("fma.rn.f32x2 %0, %1, %2, %3;" : "=l"(d) : "l"(a), "l"(b), "l"(c));
    return d;
}
__device__ __forceinline__ u64 pack2(float lo, float hi) {
    u64 r;
    asm("mov.b64 %0, {%1, %2};" : "=l"(r) : "f"(lo), "f"(hi));
    return r;
}
__device__ __forceinline__ float2 unpack2(u64 v) {
    float lo, hi;
    asm("mov.b64 {%0, %1}, %2;" : "=f"(lo), "=f"(hi) : "l"(v));
    return make_float2(lo, hi);
}

// ---------------------------------------------------------------- zero
__global__ void k_zero(int n) {
    int i = blockIdx.x * 256 + threadIdx.x;
    if (i < n) g_deg[i] = 0;
    if (i == 0) g_sum = 0.0;
}

// ---------------------------------------------------------------- degree count only
__global__ void k_prep(const int* __restrict__ ei, int E) {
    int e = blockIdx.x * 256 + threadIdx.x;
    if (e < E) atomicAdd(&g_deg[ei[e]], 1);
}

// ---------------------------------------------------------------- multi-block exclusive scan
__global__ void k_scan1(int n) {
    int base = blockIdx.x * 1024 + threadIdx.x * 4;
    int d0 = 0, d1 = 0, d2 = 0, d3 = 0;
    if (base + 3 < n) {
        int4 v = *(const int4*)&g_deg[base];
        d0 = v.x; d1 = v.y; d2 = v.z; d3 = v.w;
    } else {
        if (base + 0 < n) d0 = g_deg[base + 0];
        if (base + 1 < n) d1 = g_deg[base + 1];
        if (base + 2 < n) d2 = g_deg[base + 2];
        if (base + 3 < n) d3 = g_deg[base + 3];
    }
    int s = d0 + d1 + d2 + d3;
    int lane = threadIdx.x & 31, wid = threadIdx.x >> 5;
    int v = s;
#pragma unroll
    for (int o = 1; o < 32; o <<= 1) {
        int y = __shfl_up_sync(0xffffffffu, v, o);
        if (lane >= o) v += y;
    }
    __shared__ int ws[8];
    if (lane == 31) ws[wid] = v;
    __syncthreads();
    if (threadIdx.x == 0) {
        int run = 0;
#pragma unroll
        for (int i = 0; i < 8; i++) { int t = ws[i]; ws[i] = run; run += t; }
        g_bsum[blockIdx.x] = run;
    }
    __syncthreads();
    int excl = v - s + ws[wid];
    if (base + 0 < n) g_off[base + 0] = excl;
    if (base + 1 < n) g_off[base + 1] = excl + d0;
    if (base + 2 < n) g_off[base + 2] = excl + d0 + d1;
    if (base + 3 < n) g_off[base + 3] = excl + d0 + d1 + d2;
}

// ---------------------------------------------------------------- xw = x @ W1[:64,:] + b1
// 128 nodes x 64 cols per block, 256 threads: 8 nodes x 4 cols per thread
// as 4 node-pairs with fma.rn.f32x2. K split into two 32-dim passes so
// smem fits: xs[32][132] (16.9KB) + ws (16KB) = 33.3KB.
__global__ void __launch_bounds__(256) k_xw(const float* __restrict__ x,
                                            const float* __restrict__ W1,
                                            const float* __restrict__ b1, int n) {
    __shared__ float xs[32 * 132];
    __shared__ float ws[64 * 64];
    int n0 = blockIdx.x * 128;
    for (int i = threadIdx.x; i < 4096; i += 256) ws[i] = W1[i];

    int tx = threadIdx.x & 15, ty = threadIdx.x >> 4;
    float4 bq = *(const float4*)&b1[tx * 4];
    u64 acc[4][4];
#pragma unroll
    for (int j = 0; j < 4; j++) {
        acc[j][0] = pack2(bq.x, bq.x);
        acc[j][1] = pack2(bq.y, bq.y);
        acc[j][2] = pack2(bq.z, bq.z);
        acc[j][3] = pack2(bq.w, bq.w);
    }
    const float* xrow = &xs[ty * 8];
    const float* wrow = &ws[tx * 4];

#pragma unroll
    for (int pass = 0; pass < 2; pass++) {
        __syncthreads();   // first iter: covers ws; later: xs reuse
        // load 128 nodes x 32 dims (this pass's K-half), transposed
        for (int i = threadIdx.x; i < 128 * 8; i += 256) {
            int node = i >> 3, cq = (i & 7) * 4;
            float4 v = make_float4(0.f, 0.f, 0.f, 0.f);
            if (n0 + node < n)
                v = *(const float4*)&x[(size_t)(n0 + node) * 64 + pass * 32 + cq];
            xs[(cq + 0) * 132 + node] = v.x;
            xs[(cq + 1) * 132 + node] = v.y;
            xs[(cq + 2) * 132 + node] = v.z;
            xs[(cq + 3) * 132 + node] = v.w;
        }
        __syncthreads();
#pragma unroll 8
        for (int dd = 0; dd < 32; dd++) {
            int d = pass * 32 + dd;
            float4 a0 = *(const float4*)&xrow[dd * 132];
            float4 a1 = *(const float4*)&xrow[dd * 132 + 4];
            float4 w  = *(const float4*)&wrow[d * 64];
            u64 p0 = pack2(a0.x, a0.y);
            u64 p1 = pack2(a0.z, a0.w);
            u64 p2 = pack2(a1.x, a1.y);
            u64 p3 = pack2(a1.z, a1.w);
            u64 w0 = pack2(w.x, w.x), w1 = pack2(w.y, w.y);
            u64 w2 = pack2(w.z, w.z), w3 = pack2(w.w, w.w);
            acc[0][0] = ffma2(p0, w0, acc[0][0]); acc[0][1] = ffma2(p0, w1, acc[0][1]);
            acc[0][2] = ffma2(p0, w2, acc[0][2]); acc[0][3] = ffma2(p0, w3, acc[0][3]);
            acc[1][0] = ffma2(p1, w0, acc[1][0]); acc[1][1] = ffma2(p1, w1, acc[1][1]);
            acc[1][2] = ffma2(p1, w2, acc[1][2]); acc[1][3] = ffma2(p1, w3, acc[1][3]);
            acc[2][0] = ffma2(p2, w0, acc[2][0]); acc[2][1] = ffma2(p2, w1, acc[2][1]);
            acc[2][2] = ffma2(p2, w2, acc[2][2]); acc[2][3] = ffma2(p2, w3, acc[2][3]);
            acc[3][0] = ffma2(p3, w0, acc[3][0]); acc[3][1] = ffma2(p3, w1, acc[3][1]);
            acc[3][2] = ffma2(p3, w2, acc[3][2]); acc[3][3] = ffma2(p3, w3, acc[3][3]);
        }
    }
#pragma unroll
    for (int j = 0; j < 4; j++) {
        float2 c0 = unpack2(acc[j][0]);
        float2 c1 = unpack2(acc[j][1]);
        float2 c2 = unpack2(acc[j][2]);
        float2 c3 = unpack2(acc[j][3]);
        int ne = n0 + ty * 8 + 2 * j;
        if (ne < n)
            *(float4*)&g_xw[(size_t)ne * 64 + tx * 4] = make_float4(c0.x, c1.x, c2.x, c3.x);
        if (ne + 1 < n)
            *(float4*)&g_xw[(size_t)(ne + 1) * 64 + tx * 4] = make_float4(c0.y, c1.y, c2.y, c3.y);
    }
}

// ---------------------------------------------------------------- pack pos+nrm (32B/node)
__global__ void k_pack(const float* __restrict__ pos, const float* __restrict__ nrm, int n) {
    int i = blockIdx.x * 256 + threadIdx.x;
    if (i < n) {
        g_pn[2 * i + 0] = make_float4(pos[3 * i], pos[3 * i + 1], pos[3 * i + 2], 0.f);
        g_pn[2 * i + 1] = make_float4(nrm[3 * i], nrm[3 * i + 1], nrm[3 * i + 2], 0.f);
    }
}

// Stage 2: scan block sums; g_off[n]=E.
__global__ void k_scan2(int nb, int n, int E) {
    int t = threadIdx.x;  // blockDim = 128
    int s = (t < nb) ? g_bsum[t] : 0;
    int lane = t & 31, wid = t >> 5;
    int v = s;
#pragma unroll
    for (int o = 1; o < 32; o <<= 1) {
        int y = __shfl_up_sync(0xffffffffu, v, o);
        if (lane >= o) v += y;
    }
    __shared__ int ws[4];
    if (lane == 31) ws[wid] = v;
    __syncthreads();
    if (t == 0) {
        int run = 0;
#pragma unroll
        for (int i = 0; i < 4; i++) { int x = ws[i]; ws[i] = run; run += x; }
    }
    __syncthreads();
    int excl = v - s + ws[wid];
    if (t < nb) g_bsum[t] = excl;
    if (t == 0) g_off[n] = E;
}

// Stage 3: add block offsets; init g_cur.
__global__ void k_scan3(int n) {
    int i = blockIdx.x * 256 + threadIdx.x;
    if (i >= n) return;
    int o = g_off[i] + g_bsum[i >> 10];
    g_off[i] = o;
    g_cur[i] = o;
}

// ---------------------------------------------------------------- ppf + scatter + dist sum
__device__ __forceinline__ float ppf_angle(float ax, float ay, float az,
                                           float bx, float by, float bz) {
    float cx = ay * bz - az * by;
    float cy = az * bx - ax * bz;
    float cz = ax * by - ay * bx;
    float dot = ax * bx + ay * by + az * bz;
    return atan2f(sqrtf(cx * cx + cy * cy + cz * cz), dot);
}

__global__ void k_scatter(const int* __restrict__ ei, int E) {
    int e = blockIdx.x * 256 + threadIdx.x;
    float dist = 0.f;
    if (e < E) {
        int r = ei[e], c = ei[E + e];
        float4 pr = g_pn[2 * r + 0];
        float4 n1 = g_pn[2 * r + 1];
        float4 pc = g_pn[2 * c + 0];
        float4 n2 = g_pn[2 * c + 1];
        float dx = pc.x - pr.x;
        float dy = pc.y - pr.y;
        float dz = pc.z - pr.z;
        dist = dx * dx + dy * dy + dz * dz;
        float a1 = ppf_angle(n1.x, n1.y, n1.z, dx, dy, dz);
        float a2 = ppf_angle(n2.x, n2.y, n2.z, dx, dy, dz);
        float a3 = ppf_angle(n1.x, n1.y, n1.z, n2.x, n2.y, n2.z);
        int p = atomicAdd(&g_cur[r], 1);
        float4* dst = (float4*)&g_rec[p];
        dst[0] = make_float4(dist, a1, a2, a3);   // raw dist; inv folded into w0 later
        dst[1] = make_float4(__int_as_float(c), 0.f, 0.f, 0.f);
    }
#pragma unroll
    for (int o = 16; o > 0; o >>= 1) dist += __shfl_down_sync(0xffffffffu, dist, o);
    __shared__ float wpart[8];
    int lane = threadIdx.x & 31, wid = threadIdx.x >> 5;
    if (lane == 0) wpart[wid] = dist;
    __syncthreads();
    if (threadIdx.x == 0) {
        float s = 0.f;
#pragma unroll
        for (int i = 0; i < 8; i++) s += wpart[i];
        atomicAdd(&g_sum, (double)s);
    }
}

// ---------------------------------------------------------------- normalizer
__global__ void k_mean(int n, int E) {
    g_invmean = (float)((double)(E + n) / g_sum);
}

// ---------------------------------------------------------------- fused: segmax (4 nodes/warp) + relu(seg @ W2 + b2)
__global__ void __launch_bounds__(256) k_node_out(const float* __restrict__ W1,
                                                  const float* __restrict__ W2,
                                                  const float* __restrict__ b2,
                                                  float* __restrict__ out, int n) {
    __shared__ float ws[64 * 128];
    __shared__ float sdup[8][4 * 128];   // [warp][node k][dup dims]
    for (int i = threadIdx.x; i < 64 * 128; i += 256) ws[i] = W2[i];
    __syncthreads();

    int lane = threadIdx.x & 31;
    int wid  = threadIdx.x >> 5;

    float inv = g_invmean;
    const float* Wp = W1 + 64 * 64;
    float2 w0 = *(const float2*)&Wp[0 * 64 + lane * 2];
    w0.x *= inv; w0.y *= inv;                   // fold dist normalization into w0
    float2 w1 = *(const float2*)&Wp[1 * 64 + lane * 2];
    float2 w2 = *(const float2*)&Wp[2 * 64 + lane * 2];
    float2 w3 = *(const float2*)&Wp[3 * 64 + lane * 2];
    float4 bq = *(const float4*)&b2[lane * 4];
    u64 bb0 = pack2(bq.x, bq.y);
    u64 bb1 = pack2(bq.z, bq.w);

    int step = gridDim.x * 8 * 4;
    for (int base = (blockIdx.x * 8 + wid) * 4; base < n; base += step) {
        // phase 1: segment-max for 4 consecutive nodes
#pragma unroll
        for (int k = 0; k < 4; k++) {
            int node = base + k;
            float ax = 0.f, ay = 0.f;
            if (node < n) {
                float2 xw = *(const float2*)&g_xw[(size_t)node * 64 + lane * 2];
                ax = fmaxf(xw.x, 0.f);   // self-loop: ppf == 0 exactly
                ay = fmaxf(xw.y, 0.f);
                int beg = g_off[node];
                int end = g_off[node + 1];
                int i = beg;
                for (; i + 1 < end; i += 2) {
                    const float4* r0 = (const float4*)&g_rec[i];
                    const float4* r1 = (const float4*)&g_rec[i + 1];
                    float4 p0 = r0[0];
                    float4 p1 = r1[0];
                    int c0 = __float_as_int(r0[1].x);
                    int c1 = __float_as_int(r1[1].x);
                    float2 xc0 = *(const float2*)&g_xw[(size_t)c0 * 64 + lane * 2];
                    float2 xc1 = *(const float2*)&g_xw[(size_t)c1 * 64 + lane * 2];
                    float hx0 = fmaf(p0.x, w0.x, fmaf(p0.y, w1.x, fmaf(p0.z, w2.x, fmaf(p0.w, w3.x, xc0.x))));
                    float hy0 = fmaf(p0.x, w0.y, fmaf(p0.y, w1.y, fmaf(p0.z, w2.y, fmaf(p0.w, w3.y, xc0.y))));
                    float hx1 = fmaf(p1.x, w0.x, fmaf(p1.y, w1.x, fmaf(p1.z, w2.x, fmaf(p1.w, w3.x, xc1.x))));
                    float hy1 = fmaf(p1.x, w0.y, fmaf(p1.y, w1.y, fmaf(p1.z, w2.y, fmaf(p1.w, w3.y, xc1.y))));
                    ax = fmaxf(ax, fmaxf(hx0, hx1));
                    ay = fmaxf(ay, fmaxf(hy0, hy1));
                }
                if (i < end) {
                    const float4* r0 = (const float4*)&g_rec[i];
                    float4 p = r0[0];
                    int c = __float_as_int(r0[1].x);
                    float2 xc = *(const float2*)&g_xw[(size_t)c * 64 + lane * 2];
                    float hx = fmaf(p.x, w0.x, fmaf(p.y, w1.x, fmaf(p.z, w2.x, fmaf(p.w, w3.x, xc.x))));
                    float hy = fmaf(p.x, w0.y, fmaf(p.y, w1.y, fmaf(p.z, w2.y, fmaf(p.w, w3.y, xc.y))));
                    ax = fmaxf(ax, hx);
                    ay = fmaxf(ay, hy);
                }
            }
            *(float4*)&sdup[wid][k * 128 + lane * 4] = make_float4(ax, ax, ay, ay);
        }
        __syncwarp();

        // phase 2: GEMV for 4 nodes with shared W2 reads + f32x2
        u64 a0x = bb0, a0y = bb1;
        u64 a1x = bb0, a1y = bb1;
        u64 a2x = bb0, a2y = bb1;
        u64 a3x = bb0, a3y = bb1;
#pragma unroll 8
        for (int jp = 0; jp < 32; jp++) {
            float4 wAf = *(const float4*)&ws[(2 * jp) * 128 + lane * 4];
            float4 wBf = *(const float4*)&ws[(2 * jp + 1) * 128 + lane * 4];
            float4 s0f = *(const float4*)&sdup[wid][0 * 128 + jp * 4];
            float4 s1f = *(const float4*)&sdup[wid][1 * 128 + jp * 4];
            float4 s2f = *(const float4*)&sdup[wid][2 * 128 + jp * 4];
            float4 s3f = *(const float4*)&sdup[wid][3 * 128 + jp * 4];
            u64 wAx = pack2(wAf.x, wAf.y), wAy = pack2(wAf.z, wAf.w);
            u64 wBx = pack2(wBf.x, wBf.y), wBy = pack2(wBf.z, wBf.w);
            u64 s0a = pack2(s0f.x, s0f.y), s0b = pack2(s0f.z, s0f.w);
            u64 s1a = pack2(s1f.x, s1f.y), s1b = pack2(s1f.z, s1f.w);
            u64 s2a = pack2(s2f.x, s2f.y), s2b = pack2(s2f.z, s2f.w);
            u64 s3a = pack2(s3f.x, s3f.y), s3b = pack2(s3f.z, s3f.w);
            a0x = ffma2(s0a, wAx, a0x); a0y = ffma2(s0a, wAy, a0y);
            a0x = ffma2(s0b, wBx, a0x); a0y = ffma2(s0b, wBy, a0y);
            a1x = ffma2(s1a, wAx, a1x); a1y = ffma2(s1a, wAy, a1y);
            a1x = ffma2(s1b, wBx, a1x); a1y = ffma2(s1b, wBy, a1y);
            a2x = ffma2(s2a, wAx, a2x); a2y = ffma2(s2a, wAy, a2y);
            a2x = ffma2(s2b, wBx, a2x); a2y = ffma2(s2b, wBy, a2y);
            a3x = ffma2(s3a, wAx, a3x); a3y = ffma2(s3a, wAy, a3y);
            a3x = ffma2(s3b, wBx, a3x); a3y = ffma2(s3b, wBy, a3y);
        }
        __syncwarp();

        u64 rx[4] = {a0x, a1x, a2x, a3x};
        u64 ry[4] = {a0y, a1y, a2y, a3y};
#pragma unroll
        for (int k = 0; k < 4; k++) {
            int node = base + k;
            if (node < n) {
                float2 lo = unpack2(rx[k]);
                float2 hi = unpack2(ry[k]);
                float4 o = make_float4(fmaxf(lo.x, 0.f), fmaxf(lo.y, 0.f),
                                       fmaxf(hi.x, 0.f), fmaxf(hi.y, 0.f));
                *(float4*)&out[(size_t)node * 128 + lane * 4] = o;
            }
        }
    }
}

// ---------------------------------------------------------------- launch
extern "C" void kernel_launch(void* const* d_in, const int* in_sizes, int n_in,
                              void* d_out, int out_size) {
    const float* x   = (const float*)d_in[0];
    const float* pos = (const float*)d_in[1];
    const float* nrm = (const float*)d_in[2];
    const int*   ei  = (const int*)d_in[3];
    // d_in[4] = batch (unused)
    const float* W1  = (const float*)d_in[5];
    const float* b1  = (const float*)d_in[6];
    const float* W2  = (const float*)d_in[7];
    const float* b2  = (const float*)d_in[8];
    float* out = (float*)d_out;

    int N = in_sizes[1] / 3;
    int E = in_sizes[3] / 2;
    int nb = (N + 1023) / 1024;

    k_zero<<<(N + 255) / 256, 256>>>(N);
    k_prep<<<(E + 255) / 256, 256>>>(ei, E);
    k_scan1<<<nb, 256>>>(N);
    k_xw<<<(N + 127) / 128, 256>>>(x, W1, b1, N);   // launch #4 -> profiled
    k_pack<<<(N + 255) / 256, 256>>>(pos, nrm, N);
    k_scan2<<<1, 128>>>(nb, N, E);
    k_scan3<<<(N + 255) / 256, 256>>>(N);
    k_scatter<<<(E + 255) / 256, 256>>>(ei, E);
    k_mean<<<1, 1>>>(N, E);
    k_node_out<<<592, 256>>>(W1, W2, b2, out, N);
}